// round 3
// baseline (speedup 1.0000x reference)
#include <cuda_runtime.h>
#include <cub/cub.cuh>

// Problem shape: input [8,64,256,256], target [8,64,128,128]
#define NSEG   512
#define S_LEN  65536
#define R_LEN  16384
#define N_SRC  (NSEG * S_LEN)
#define N_TGT  (NSEG * R_LEN)

// custom segmented radix config
#define TPB    256
#define NWARP  8
#define UPT    8
#define TILE   (TPB * UPT)        // 2048
#define NTILE  (S_LEN / TILE)     // 32
#define BINS   4096
#define SMEM_WORDS (BINS + BINS * 4 + 64)
#define SMEM_BYTES (SMEM_WORDS * 4)   // 82,176 B

// ---------------- static device scratch ------------------------------------
__device__ unsigned int   g_k0[N_SRC];
__device__ unsigned int   g_k1[N_SRC];
__device__ unsigned short g_v0[N_SRC];
__device__ unsigned short g_v1[N_SRC];
__device__ float          g_tkeys_a[N_TGT];
__device__ float          g_tkeys_b[N_TGT];
__device__ int            g_toff[NSEG + 1];
__device__ double         g_accum;
#define TEMP_BYTES (32u << 20)
__device__ unsigned char  g_temp[TEMP_BYTES];

// ---------------- kernels --------------------------------------------------

__global__ void init_k() {
    int i = blockIdx.x * blockDim.x + threadIdx.x;
    if (i <= NSEG) g_toff[i] = i * R_LEN;
    if (i == 0) g_accum = 0.0;
}

// 24-bit monotone quantized key + 16-bit per-row index payload.
__global__ void fill_src_k(const float* __restrict__ in) {
    int i = blockIdx.x * blockDim.x + threadIdx.x;
    if (i < N_SRC) {
        unsigned int u = __float_as_uint(in[i]);
        u ^= (u & 0x80000000u) ? 0xFFFFFFFFu : 0x80000000u;
        g_k0[i] = u >> 8;
        g_v0[i] = (unsigned short)(i & 0xFFFF);
    }
}

// One CTA per row. Stable 12-bit-digit counting-sort pass.
template <int SHIFT, bool WRITE_KEYS>
__global__ __launch_bounds__(TPB)
void sortpass_k(const unsigned int* __restrict__ kin,
                const unsigned short* __restrict__ vin,
                unsigned int* __restrict__ kout,
                unsigned short* __restrict__ vout) {
    extern __shared__ unsigned int sm[];
    unsigned int* offs = sm;             // [BINS] row cdf -> running offsets
    unsigned int* wcnt = sm + BINS;      // [BINS][4] packed per-warp counters
    unsigned int* ws   = sm + BINS * 5;  // scan scratch

    const int row = blockIdx.x;
    const unsigned int rowbase = (unsigned)row << 16;
    const int tid  = threadIdx.x;
    const int lane = tid & 31;
    const int w    = tid >> 5;

    // ---- Phase A: whole-row histogram ----
    #pragma unroll
    for (int j = 0; j < BINS / TPB; j++) offs[tid + j * TPB] = 0;
    __syncthreads();
    for (int i = tid; i < S_LEN; i += TPB) {
        unsigned int d = (kin[rowbase + i] >> SHIFT) & (BINS - 1);
        unsigned int m = __match_any_sync(0xffffffffu, d);
        if (lane == __ffs(m) - 1) atomicAdd(&offs[d], __popc(m));
    }
    __syncthreads();

    // ---- exclusive scan of 4096 bins (in place) ----
    unsigned int loc[16];
    const unsigned int base = tid * 16;
    unsigned int run = 0;
    #pragma unroll
    for (int j = 0; j < 16; j++) { loc[j] = run; run += offs[base + j]; }
    unsigned int incl = run;
    #pragma unroll
    for (int o = 1; o < 32; o <<= 1) {
        unsigned int t = __shfl_up_sync(0xffffffffu, incl, o);
        if (lane >= o) incl += t;
    }
    if (lane == 31) ws[w] = incl;
    __syncthreads();
    if (tid < NWARP) {
        unsigned int v = ws[tid];
        #pragma unroll
        for (int o = 1; o < NWARP; o <<= 1) {
            unsigned int t = __shfl_up_sync(0xffu, v, o);
            if (tid >= o) v += t;
        }
        ws[tid] = v;  // inclusive warp totals
    }
    __syncthreads();
    unsigned int wpref = (w == 0) ? 0u : ws[w - 1];
    unsigned int tpref = wpref + (incl - run);
    #pragma unroll
    for (int j = 0; j < 16; j++) offs[base + j] = tpref + loc[j];
    __syncthreads();

    // ---- Phase B: stable scatter, tile by tile ----
    for (int t = 0; t < NTILE; t++) {
        uint4* wc4 = (uint4*)wcnt;
        #pragma unroll
        for (int j = 0; j < (BINS * 4) / (TPB * 4); j++)
            wc4[tid + j * TPB] = make_uint4(0, 0, 0, 0);
        __syncthreads();

        unsigned int   kreg[UPT], dreg[UPT], rreg[UPT];
        unsigned short vreg[UPT];
        const unsigned int ebase = rowbase + t * TILE + w * (32 * UPT) + lane;
        #pragma unroll
        for (int u = 0; u < UPT; u++) {
            kreg[u] = kin[ebase + u * 32];
            vreg[u] = vin[ebase + u * 32];
        }
        // stable in-warp ranking; per-warp running counters (2 warps / u32)
        #pragma unroll
        for (int u = 0; u < UPT; u++) {
            unsigned int d = (kreg[u] >> SHIFT) & (BINS - 1);
            dreg[u] = d;
            unsigned int m = __match_any_sync(0xffffffffu, d);
            int leader = __ffs(m) - 1;
            unsigned int cnt = __popc(m);
            unsigned int old = 0;
            if (lane == leader)
                old = atomicAdd(&wcnt[d * 4 + (w >> 1)],
                                (w & 1) ? (cnt << 16) : cnt);
            old = __shfl_sync(0xffffffffu, old, leader);
            unsigned int prev = (w & 1) ? (old >> 16) : (old & 0xffffu);
            rreg[u] = prev + __popc(m & ((1u << lane) - 1u));
        }
        __syncthreads();
        // inter-warp prefix + write out
        #pragma unroll
        for (int u = 0; u < UPT; u++) {
            unsigned int d = dreg[u];
            uint4 q = ((const uint4*)wcnt)[d];
            unsigned int wp = 0;
            if (w > 0) wp += q.x & 0xffffu;
            if (w > 1) wp += q.x >> 16;
            if (w > 2) wp += q.y & 0xffffu;
            if (w > 3) wp += q.y >> 16;
            if (w > 4) wp += q.z & 0xffffu;
            if (w > 5) wp += q.z >> 16;
            if (w > 6) wp += q.w & 0xffffu;
            unsigned int pos = rowbase + offs[d] + wp + rreg[u];
            if (WRITE_KEYS) kout[pos] = kreg[u];
            vout[pos] = vreg[u];
        }
        __syncthreads();
        // advance running offsets by tile totals
        #pragma unroll
        for (int j = 0; j < BINS / TPB; j++) {
            unsigned int b = tid + j * TPB;
            uint4 q = ((const uint4*)wcnt)[b];
            unsigned int tot = (q.x & 0xffffu) + (q.x >> 16)
                             + (q.y & 0xffffu) + (q.y >> 16)
                             + (q.z & 0xffffu) + (q.z >> 16)
                             + (q.w & 0xffffu) + (q.w >> 16);
            offs[b] += tot;
        }
        __syncthreads();
    }
}

// Fused resample + scatter + loss.
__global__ void scatter_k(const unsigned short* __restrict__ svals,
                          const float* __restrict__ tkeys,
                          const float* __restrict__ input,
                          float* __restrict__ matched) {
    const int i = blockIdx.x * blockDim.x + threadIdx.x;
    const int row = i >> 16;
    const int j   = i & 0xFFFF;

    const float step = (float)(R_LEN - 1) / (float)(S_LEN - 1);
    float pos = (float)j * step;
    int lo = (int)pos;
    if (lo > R_LEN - 1) lo = R_LEN - 1;
    float w = pos - (float)lo;
    int hi = lo + (w > 0.0f ? 1 : 0);
    if (hi > R_LEN - 1) hi = R_LEN - 1;

    const float* __restrict__ refrow = tkeys + (size_t)row * R_LEN;
    float a = __ldg(refrow + lo);
    float b = __ldg(refrow + hi);
    float val = a * (1.0f - w) + b * w;

    const size_t p = ((size_t)row << 16) + (size_t)svals[i];
    float x = __ldg(input + p);
    matched[p] = val;

    float d = x - val;
    double sq = (double)d * (double)d;
    #pragma unroll
    for (int o = 16; o > 0; o >>= 1)
        sq += __shfl_down_sync(0xFFFFFFFFu, sq, o);
    __shared__ double ssum[8];
    int lane = threadIdx.x & 31, warp = threadIdx.x >> 5;
    if (lane == 0) ssum[warp] = sq;
    __syncthreads();
    if (threadIdx.x == 0) {
        double s = 0.0;
        #pragma unroll
        for (int k = 0; k < 8; k++) s += ssum[k];
        atomicAdd(&g_accum, s);
    }
}

__global__ void fin_k(float* __restrict__ out_loss) {
    *out_loss = (float)(g_accum / (double)N_SRC);
}

// ---------------- launch ---------------------------------------------------

extern "C" void kernel_launch(void* const* d_in, const int* in_sizes, int n_in,
                              void* d_out, int out_size) {
    const float* input  = (const float*)d_in[0];
    const float* target = (const float*)d_in[1];
    float* out = (float*)d_out;

    unsigned int *k0, *k1;
    unsigned short *v0, *v1;
    float *tkeys_a, *tkeys_b;
    int *toff;
    void* temp;
    cudaGetSymbolAddress((void**)&k0, g_k0);
    cudaGetSymbolAddress((void**)&k1, g_k1);
    cudaGetSymbolAddress((void**)&v0, g_v0);
    cudaGetSymbolAddress((void**)&v1, g_v1);
    cudaGetSymbolAddress((void**)&tkeys_a, g_tkeys_a);
    cudaGetSymbolAddress((void**)&tkeys_b, g_tkeys_b);
    cudaGetSymbolAddress((void**)&toff,    g_toff);
    cudaGetSymbolAddress(&temp,            g_temp);

    cudaFuncSetAttribute(sortpass_k<0, true>,
                         cudaFuncAttributeMaxDynamicSharedMemorySize, SMEM_BYTES);
    cudaFuncSetAttribute(sortpass_k<12, false>,
                         cudaFuncAttributeMaxDynamicSharedMemorySize, SMEM_BYTES);

    init_k<<<1, 1024>>>();
    fill_src_k<<<N_SRC / 256, 256>>>(input);
    cudaMemcpyAsync(tkeys_a, target, (size_t)N_TGT * sizeof(float),
                    cudaMemcpyDeviceToDevice, 0);

    // ---- target: exact segmented sort (CUB) ----
    cub::DoubleBuffer<float> dtk(tkeys_a, tkeys_b);
    size_t tb_t = 0;
    cub::DeviceSegmentedRadixSort::SortKeys(nullptr, tb_t, dtk, N_TGT, NSEG,
                                            toff, toff + 1, 0, 32, 0);
    if (tb_t > TEMP_BYTES) return;
    cub::DeviceSegmentedRadixSort::SortKeys(temp, tb_t, dtk, N_TGT, NSEG,
                                            toff, toff + 1, 0, 32, 0);

    // ---- source: custom 2-pass segmented radix (24-bit quantized keys) ----
    sortpass_k<0,  true ><<<NSEG, TPB, SMEM_BYTES>>>(k0, v0, k1, v1);
    sortpass_k<12, false><<<NSEG, TPB, SMEM_BYTES>>>(k1, v1, nullptr, v0);

    // ---- resample + scatter + loss ----
    scatter_k<<<N_SRC / 256, 256>>>(v0, dtk.Current(), input, out);

    if (out_size > N_SRC)
        fin_k<<<1, 1>>>(out + (out_size - 1));
}